// round 1
// baseline (speedup 1.0000x reference)
#include <cuda_runtime.h>
#include <cstddef>

#define DIM   4096
#define H3    12288
#define FFN_D 16384
#define NT    2048      // total tokens = 2*1024
#define LR    16        // lora rank
#define SEQ   1024
#define NH    32
#define HD    128

// ---------------- scratch (device globals; no allocations allowed) ----------
__device__ float g_ln1 [(size_t)NT * DIM];
__device__ float g_qkv [(size_t)NT * H3];
__device__ float g_attn[(size_t)NT * DIM];
__device__ float g_res2[(size_t)NT * DIM];
__device__ float g_ln2 [(size_t)NT * DIM];
__device__ float g_h1  [(size_t)NT * FFN_D];
__device__ float g_u   [(size_t)NT * LR];

// ---------------- LayerNorm: one block per row --------------------------------
__global__ void ln_kernel(const float* __restrict__ x, const float* __restrict__ g,
                          const float* __restrict__ b, float* __restrict__ out) {
    int row = blockIdx.x;
    const float* xr = x + (size_t)row * DIM;
    float* orow = out + (size_t)row * DIM;
    int tid = threadIdx.x;
    float s = 0.f, s2 = 0.f;
    for (int i = tid; i < DIM; i += 256) { float v = xr[i]; s += v; s2 += v * v; }
    __shared__ float rs[8], rs2[8];
    #pragma unroll
    for (int o = 16; o; o >>= 1) {
        s  += __shfl_xor_sync(0xffffffffu, s,  o);
        s2 += __shfl_xor_sync(0xffffffffu, s2, o);
    }
    int warp = tid >> 5, lane = tid & 31;
    if (!lane) { rs[warp] = s; rs2[warp] = s2; }
    __syncthreads();
    s = 0.f; s2 = 0.f;
    #pragma unroll
    for (int w = 0; w < 8; w++) { s += rs[w]; s2 += rs2[w]; }
    float mean = s * (1.f / DIM);
    float var  = s2 * (1.f / DIM) - mean * mean;
    float rstd = rsqrtf(var + 1e-5f);
    for (int i = tid; i < DIM; i += 256) {
        float v = xr[i];
        orow[i] = (v - mean) * rstd * g[i] + b[i];
    }
}

// ---------------- LoRA "u" = x @ A^T  (per-token adapter) ---------------------
// A: [NA, LR, K].  u: [NT, LR].  One block (256 thr = 8 warps) per token; each
// warp reduces 2 of the 16 ranks.
__global__ void lora_u_kernel(const float* __restrict__ x, const float* __restrict__ A,
                              const int* __restrict__ map, float* __restrict__ u, int K) {
    int t = blockIdx.x;
    int a = map[t];
    const float* xr = x + (size_t)t * K;
    int warp = threadIdx.x >> 5, lane = threadIdx.x & 31;
    #pragma unroll
    for (int rr = 0; rr < 2; rr++) {
        int r = warp * 2 + rr;
        const float* ar = A + ((size_t)a * LR + r) * K;
        float s = 0.f;
        for (int i = lane; i < K; i += 32) s += xr[i] * ar[i];
        #pragma unroll
        for (int o = 16; o; o >>= 1) s += __shfl_xor_sync(0xffffffffu, s, o);
        if (!lane) u[t * LR + r] = s;
    }
}

// ---------------- GEMM:  C[m,n] = sum_k A[m,k] * W[n,k]  ----------------------
// A row-major [M,K]; W row-major [N,K] (i.e., C = A @ W^T).
// Epilogue: + bias[n] + sum_r u[m,r]*Bl[a_m, n, r]  (+ resid)  (relu?)
// Tiles: 128x128x16, 256 threads, 8x8 micro-tile per thread.
#define BM 128
#define BN 128
#define BK 16
__global__ __launch_bounds__(256, 2)
void gemm_kernel(const float* __restrict__ A, const float* __restrict__ W,
                 const float* __restrict__ bias, const float* __restrict__ u,
                 const float* __restrict__ Bl, const int* __restrict__ map,
                 const float* __restrict__ resid, float* __restrict__ C,
                 int M, int N, int K, int relu) {
    __shared__ float As[BK][BM];
    __shared__ float Ws[BK][BN];
    int tid = threadIdx.x;
    int tx = tid & 15;        // 0..15 -> n
    int ty = tid >> 4;        // 0..15 -> m
    int m0 = blockIdx.y * BM;
    int n0 = blockIdx.x * BN;
    float acc[8][8];
    #pragma unroll
    for (int i = 0; i < 8; i++)
        #pragma unroll
        for (int j = 0; j < 8; j++) acc[i][j] = 0.f;

    for (int k0 = 0; k0 < K; k0 += BK) {
        // load 128x16 A-tile and 128x16 W-tile (512 float4 each; 2 per thread)
        #pragma unroll
        for (int l = 0; l < 2; l++) {
            int idx = tid + l * 256;
            int r  = idx >> 2;             // 0..127
            int kv = (idx & 3) << 2;       // 0,4,8,12
            float4 av = *(const float4*)(A + (size_t)(m0 + r) * K + k0 + kv);
            As[kv + 0][r] = av.x; As[kv + 1][r] = av.y;
            As[kv + 2][r] = av.z; As[kv + 3][r] = av.w;
            float4 wv = *(const float4*)(W + (size_t)(n0 + r) * K + k0 + kv);
            Ws[kv + 0][r] = wv.x; Ws[kv + 1][r] = wv.y;
            Ws[kv + 2][r] = wv.z; Ws[kv + 3][r] = wv.w;
        }
        __syncthreads();
        #pragma unroll
        for (int k = 0; k < BK; k++) {
            float af[8], wf[8];
            float4 a0 = *(const float4*)&As[k][ty * 8];
            float4 a1 = *(const float4*)&As[k][ty * 8 + 4];
            float4 w0 = *(const float4*)&Ws[k][tx * 8];
            float4 w1 = *(const float4*)&Ws[k][tx * 8 + 4];
            af[0]=a0.x; af[1]=a0.y; af[2]=a0.z; af[3]=a0.w;
            af[4]=a1.x; af[5]=a1.y; af[6]=a1.z; af[7]=a1.w;
            wf[0]=w0.x; wf[1]=w0.y; wf[2]=w0.z; wf[3]=w0.w;
            wf[4]=w1.x; wf[5]=w1.y; wf[6]=w1.z; wf[7]=w1.w;
            #pragma unroll
            for (int i = 0; i < 8; i++)
                #pragma unroll
                for (int j = 0; j < 8; j++) acc[i][j] += af[i] * wf[j];
        }
        __syncthreads();
    }

    // epilogue: bias + lora-B + (resid) + (relu)
    #pragma unroll
    for (int i = 0; i < 8; i++) {
        int m = m0 + ty * 8 + i;
        int a = map[m];
        float uv[LR];
        const float* up = u + (size_t)m * LR;
        #pragma unroll
        for (int r = 0; r < LR; r++) uv[r] = up[r];
        #pragma unroll
        for (int j = 0; j < 8; j++) {
            int n = n0 + tx * 8 + j;
            float v = acc[i][j] + bias[n];
            const float* brow = Bl + ((size_t)a * N + n) * LR;
            #pragma unroll
            for (int r = 0; r < LR; r++) v += uv[r] * brow[r];
            if (resid) v += resid[(size_t)m * N + n];
            if (relu) v = fmaxf(v, 0.f);
            C[(size_t)m * N + n] = v;
        }
    }
}

// ---------------- causal attention: one block (128 thr) per (b,h,q) -----------
// qkv layout: [token, 12288] with q=[0,4096), k=[4096,8192), v=[8192,12288),
// head slice h*128..+128 inside each third.
__global__ void attn_kernel(const float* __restrict__ qkv, float* __restrict__ out) {
    int qi = blockIdx.x, h = blockIdx.y, bb = blockIdx.z;
    __shared__ float qs[HD];
    __shared__ float sc[SEQ];
    __shared__ float red[4];
    const size_t base = (size_t)bb * SEQ * H3;
    int tid = threadIdx.x, lane = tid & 31, warp = tid >> 5;
    const float* qrow = qkv + base + (size_t)qi * H3 + h * HD;
    qs[tid] = qrow[tid];
    __syncthreads();
    int nk = qi + 1;
    const float scale = 0.08838834764831845f;   // 128^-0.5
    for (int k = warp; k < nk; k += 4) {
        const float* krow = qkv + base + (size_t)k * H3 + DIM + h * HD;
        float s = 0.f;
        #pragma unroll
        for (int dd = 0; dd < 4; dd++) { int d = lane + dd * 32; s += qs[d] * krow[d]; }
        #pragma unroll
        for (int o = 16; o; o >>= 1) s += __shfl_xor_sync(0xffffffffu, s, o);
        if (!lane) sc[k] = s * scale;
    }
    __syncthreads();
    // softmax
    float mx = -1e30f;
    for (int i = tid; i < nk; i += 128) mx = fmaxf(mx, sc[i]);
    #pragma unroll
    for (int o = 16; o; o >>= 1) mx = fmaxf(mx, __shfl_xor_sync(0xffffffffu, mx, o));
    if (!lane) red[warp] = mx;
    __syncthreads();
    mx = fmaxf(fmaxf(red[0], red[1]), fmaxf(red[2], red[3]));
    __syncthreads();
    float sum = 0.f;
    for (int i = tid; i < nk; i += 128) { float e = expf(sc[i] - mx); sc[i] = e; sum += e; }
    #pragma unroll
    for (int o = 16; o; o >>= 1) sum += __shfl_xor_sync(0xffffffffu, sum, o);
    if (!lane) red[warp] = sum;
    __syncthreads();
    sum = red[0] + red[1] + red[2] + red[3];
    float inv = 1.f / sum;
    // PV: thread tid owns output dim tid (coalesced v reads)
    float acc = 0.f;
    const float* vbase = qkv + base + 2 * DIM + h * HD + tid;
    for (int k = 0; k < nk; k++) acc += sc[k] * vbase[(size_t)k * H3];
    out[((size_t)bb * SEQ + qi) * DIM + h * HD + tid] = acc * inv;
}

// ---------------- launch ------------------------------------------------------
extern "C" void kernel_launch(void* const* d_in, const int* in_sizes, int n_in,
                              void* d_out, int out_size) {
    const float* x    = (const float*)d_in[0];
    const int*   map  = (const int*)  d_in[1];
    const float* Wqkv = (const float*)d_in[2];
    const float* bqkv = (const float*)d_in[3];
    const float* Wout = (const float*)d_in[4];
    const float* bout = (const float*)d_in[5];
    const float* Wfc1 = (const float*)d_in[6];
    const float* bfc1 = (const float*)d_in[7];
    const float* Wfc2 = (const float*)d_in[8];
    const float* bfc2 = (const float*)d_in[9];
    const float* ln1g = (const float*)d_in[10];
    const float* ln1b = (const float*)d_in[11];
    const float* ln2g = (const float*)d_in[12];
    const float* ln2b = (const float*)d_in[13];
    const float* Aqkv = (const float*)d_in[14];
    const float* Bqkv = (const float*)d_in[15];
    const float* Aout = (const float*)d_in[16];
    const float* Bout = (const float*)d_in[17];
    const float* Afc1 = (const float*)d_in[18];
    const float* Bfc1 = (const float*)d_in[19];
    const float* Afc2 = (const float*)d_in[20];
    const float* Bfc2 = (const float*)d_in[21];
    float* out = (float*)d_out;

    float *p_ln1, *p_qkv, *p_attn, *p_res2, *p_ln2, *p_h1, *p_u;
    cudaGetSymbolAddress((void**)&p_ln1,  g_ln1);
    cudaGetSymbolAddress((void**)&p_qkv,  g_qkv);
    cudaGetSymbolAddress((void**)&p_attn, g_attn);
    cudaGetSymbolAddress((void**)&p_res2, g_res2);
    cudaGetSymbolAddress((void**)&p_ln2,  g_ln2);
    cudaGetSymbolAddress((void**)&p_h1,   g_h1);
    cudaGetSymbolAddress((void**)&p_u,    g_u);

    // ---- attention block ----
    ln_kernel<<<NT, 256>>>(x, ln1g, ln1b, p_ln1);
    lora_u_kernel<<<NT, 256>>>(p_ln1, Aqkv, map, p_u, DIM);
    gemm_kernel<<<dim3(H3 / BN, NT / BM), 256>>>(p_ln1, Wqkv, bqkv, p_u, Bqkv, map,
                                                 nullptr, p_qkv, NT, H3, DIM, 0);
    attn_kernel<<<dim3(SEQ, NH, 2), 128>>>(p_qkv, p_attn);
    lora_u_kernel<<<NT, 256>>>(p_attn, Aout, map, p_u, DIM);
    gemm_kernel<<<dim3(DIM / BN, NT / BM), 256>>>(p_attn, Wout, bout, p_u, Bout, map,
                                                  x, p_res2, NT, DIM, DIM, 0);
    // ---- FFN block ----
    ln_kernel<<<NT, 256>>>(p_res2, ln2g, ln2b, p_ln2);
    lora_u_kernel<<<NT, 256>>>(p_ln2, Afc1, map, p_u, DIM);
    gemm_kernel<<<dim3(FFN_D / BN, NT / BM), 256>>>(p_ln2, Wfc1, bfc1, p_u, Bfc1, map,
                                                    nullptr, p_h1, NT, FFN_D, DIM, 1);
    lora_u_kernel<<<NT, 256>>>(p_h1, Afc2, map, p_u, FFN_D);
    gemm_kernel<<<dim3(DIM / BN, NT / BM), 256>>>(p_h1, Wfc2, bfc2, p_u, Bfc2, map,
                                                  p_res2, out, NT, DIM, FFN_D, 0);
}

// round 4
// speedup vs baseline: 2.4111x; 2.4111x over previous
#include <cuda_runtime.h>
#include <cuda_bf16.h>
#include <cstdint>
#include <cstddef>

#define DIM   4096
#define H3    12288
#define FFN_D 16384
#define NT    2048      // total tokens = 2*1024
#define LR    16        // lora rank
#define SEQ   1024
#define NH    32
#define HD    128

// ---------------- scratch (device globals; no allocations allowed) ----------
__device__ float g_ln1 [(size_t)NT * DIM];
__device__ float g_qkv [(size_t)NT * H3];
__device__ float g_attn[(size_t)NT * DIM];
__device__ float g_res2[(size_t)NT * DIM];
__device__ float g_ln2 [(size_t)NT * DIM];
__device__ float g_h1  [(size_t)NT * FFN_D];
__device__ float g_u   [(size_t)NT * LR];

// ================= helpers ===================================================
__device__ __forceinline__ uint32_t smem_u32(const void* p) {
    uint32_t a;
    asm("{ .reg .u64 t; cvta.to.shared.u64 t, %1; cvt.u32.u64 %0, t; }"
        : "=r"(a) : "l"(p));
    return a;
}
__device__ __forceinline__ void ldmx4(uint32_t* r, uint32_t addr) {
    asm volatile("ldmatrix.sync.aligned.m8n8.x4.shared.b16 {%0,%1,%2,%3}, [%4];"
                 : "=r"(r[0]), "=r"(r[1]), "=r"(r[2]), "=r"(r[3]) : "r"(addr));
}
__device__ __forceinline__ uint32_t lds32(uint32_t addr) {
    uint32_t v;
    asm volatile("ld.shared.b32 %0, [%1];" : "=r"(v) : "r"(addr));
    return v;
}
__device__ __forceinline__ void mma16816(float* d, const uint32_t* a,
                                         uint32_t b0, uint32_t b1) {
    asm volatile("mma.sync.aligned.m16n8k16.row.col.f32.bf16.bf16.f32 "
                 "{%0,%1,%2,%3}, {%4,%5,%6,%7}, {%8,%9}, {%0,%1,%2,%3};"
                 : "+f"(d[0]), "+f"(d[1]), "+f"(d[2]), "+f"(d[3])
                 : "r"(a[0]), "r"(a[1]), "r"(a[2]), "r"(a[3]),
                   "r"(b0), "r"(b1));
}

// ================= tensor-core GEMM (split-bf16, 3-term) ======================
// C[m,n] = sum_k A[m,k]*W[n,k] + bias[n] + sum_r u[m,r]*Bl[map[m],n,r]
//          (+ resid[m,n]) (relu?)
// Block 128x128, BK=32, 8 warps (2m x 4n), warp tile 64x32, mma m16n8k16.
#define BM 128
#define BN 128
#define BKC 32
#define RSTR 40                       // smem row stride in bf16 (pad vs banks)
#define PLANE (128 * RSTR * 2)        // 10240 B per bf16 plane
#define STAGE_B (4 * PLANE)           // A_hi | A_lo | W_hi | W_lo
#define SOFF_BIAS  128
#define SOFF_STAGE 1024
#define SMEM_G (SOFF_STAGE + 2 * STAGE_B)   // 82944

__device__ __forceinline__ void cvt_store8(float4 v, char* hi_p, char* lo_p) {
    __nv_bfloat16 h0 = __float2bfloat16(v.x), h1 = __float2bfloat16(v.y);
    __nv_bfloat16 h2 = __float2bfloat16(v.z), h3 = __float2bfloat16(v.w);
    float l0 = v.x - __bfloat162float(h0), l1 = v.y - __bfloat162float(h1);
    float l2 = v.z - __bfloat162float(h2), l3 = v.w - __bfloat162float(h3);
    __nv_bfloat162 hA(h0, h1), hB(h2, h3);
    __nv_bfloat162 lA(__float2bfloat16(l0), __float2bfloat16(l1));
    __nv_bfloat162 lB(__float2bfloat16(l2), __float2bfloat16(l3));
    uint2 hw, lw;
    hw.x = *(uint32_t*)&hA; hw.y = *(uint32_t*)&hB;
    lw.x = *(uint32_t*)&lA; lw.y = *(uint32_t*)&lB;
    *(uint2*)hi_p = hw;
    *(uint2*)lo_p = lw;
}

__device__ __forceinline__ float dot16(const float* u, const float* b) {
    float s = 0.f;
    #pragma unroll
    for (int r = 0; r < 16; r++) s = fmaf(u[r], b[r], s);
    return s;
}

__global__ void __launch_bounds__(256, 1)
tc_gemm(const float* __restrict__ A, const float* __restrict__ W,
        const float* __restrict__ bias, const float* __restrict__ u,
        const float* __restrict__ Bl, const int* __restrict__ map,
        const float* __restrict__ resid, float* __restrict__ C,
        int N, int K, int relu) {
    extern __shared__ __align__(1024) char smem[];
    uint32_t sbase = smem_u32(smem);
    int tid = threadIdx.x;
    int lane = tid & 31, warp = tid >> 5;
    int wm = warp >> 2, wn = warp & 3;
    int n0 = blockIdx.x * BN;
    int m0 = blockIdx.y * BM;

    if (tid < BN) ((float*)(smem + SOFF_BIAS))[tid] = bias[n0 + tid];

    float acc[4][4][4];
    #pragma unroll
    for (int f = 0; f < 4; f++)
        #pragma unroll
        for (int g = 0; g < 4; g++)
            #pragma unroll
            for (int e = 0; e < 4; e++) acc[f][g][e] = 0.f;

    int rowA = tid >> 3, segA = tid & 7;       // A: 128 rows x 8 segs (of 4 floats)
    const float* gA = A + (size_t)(m0 + rowA) * K + segA * 4;
    const float* gW = W + (size_t)(n0 + rowA) * K + segA * 4;
    char* stA = smem + SOFF_STAGE + rowA * (RSTR * 2) + segA * 8;

    float4 pa[4], pw[4];
    // prologue: chunk 0 into regs, then smem
    #pragma unroll
    for (int i = 0; i < 4; i++) {
        pa[i] = *(const float4*)(gA + (size_t)i * 32 * K);
        pw[i] = *(const float4*)(gW + (size_t)i * 32 * K);
    }
    #pragma unroll
    for (int i = 0; i < 4; i++) {
        char* p = stA + i * 32 * (RSTR * 2);
        cvt_store8(pa[i], p, p + PLANE);
        cvt_store8(pw[i], p + 2 * PLANE, p + 3 * PLANE);
    }
    __syncthreads();

    int lane15 = lane & 15, laneHalf = lane >> 4;
    int grp = lane >> 2, tig = lane & 3;
    int nCh = K >> 5;
    for (int c = 0; c < nCh; c++) {
        int cur = c & 1;
        if (c + 1 < nCh) {
            const float* gA2 = gA + (size_t)(c + 1) * BKC;
            const float* gW2 = gW + (size_t)(c + 1) * BKC;
            #pragma unroll
            for (int i = 0; i < 4; i++) {
                pa[i] = *(const float4*)(gA2 + (size_t)i * 32 * K);
                pw[i] = *(const float4*)(gW2 + (size_t)i * 32 * K);
            }
        }
        // ---- compute on stage cur ----
        uint32_t base = sbase + SOFF_STAGE + cur * STAGE_B;
        #pragma unroll
        for (int ks = 0; ks < 2; ks++) {
            uint32_t ahi[4][4], alo[4][4];
            int koffA = ks * 16 + laneHalf * 8;
            #pragma unroll
            for (int f = 0; f < 4; f++) {
                int row = wm * 64 + f * 16 + lane15;
                uint32_t ad = base + row * (RSTR * 2) + koffA * 2;
                ldmx4(ahi[f], ad);
                ldmx4(alo[f], ad + PLANE);
            }
            #pragma unroll
            for (int g = 0; g < 4; g++) {
                int n = wn * 32 + g * 8 + grp;
                uint32_t bd = base + 2 * PLANE + n * (RSTR * 2)
                            + (ks * 16 + tig * 2) * 2;
                uint32_t bh0 = lds32(bd), bh1 = lds32(bd + 16);
                uint32_t bl0 = lds32(bd + PLANE), bl1 = lds32(bd + PLANE + 16);
                #pragma unroll
                for (int f = 0; f < 4; f++) {
                    mma16816(acc[f][g], ahi[f], bh0, bh1);
                    mma16816(acc[f][g], ahi[f], bl0, bl1);
                    mma16816(acc[f][g], alo[f], bh0, bh1);
                }
            }
        }
        // ---- store prefetched chunk into the other stage ----
        if (c + 1 < nCh) {
            char* st2 = stA + (1 - cur) * STAGE_B;
            #pragma unroll
            for (int i = 0; i < 4; i++) {
                char* p = st2 + i * 32 * (RSTR * 2);
                cvt_store8(pa[i], p, p + PLANE);
                cvt_store8(pw[i], p + 2 * PLANE, p + 3 * PLANE);
            }
        }
        __syncthreads();
    }

    // ---- stage lora-B slice into SMEM (reuses stage area) ----
    float* Bs = (float*)(smem + SOFF_STAGE);
    for (int i = tid; i < 4096; i += 256) {   // 8 adapters * 128 n * 4 float4
        int a   = i >> 9;
        int rem = i & 511;
        int nl  = rem >> 2;
        int sg  = rem & 3;
        float4 v = *(const float4*)(Bl + ((size_t)a * N + n0 + nl) * LR + sg * 4);
        *(float4*)(Bs + ((size_t)((a << 7) + nl)) * LR + sg * 4) = v;
    }
    __syncthreads();

    const float* biasS = (const float*)(smem + SOFF_BIAS);
    #pragma unroll
    for (int f = 0; f < 4; f++) {
        int r0 = m0 + wm * 64 + f * 16 + grp;
        int r1 = r0 + 8;
        int a0 = map[r0], a1 = map[r1];
        float u0[16], u1[16];
        {
            const float4* p0 = (const float4*)(u + (size_t)r0 * LR);
            const float4* p1 = (const float4*)(u + (size_t)r1 * LR);
            #pragma unroll
            for (int q = 0; q < 4; q++) {
                float4 v0 = p0[q], v1 = p1[q];
                u0[q*4+0]=v0.x; u0[q*4+1]=v0.y; u0[q*4+2]=v0.z; u0[q*4+3]=v0.w;
                u1[q*4+0]=v1.x; u1[q*4+1]=v1.y; u1[q*4+2]=v1.z; u1[q*4+3]=v1.w;
            }
        }
        #pragma unroll
        for (int g = 0; g < 4; g++) {
            int nl = wn * 32 + g * 8 + tig * 2;
            float v00 = acc[f][g][0] + biasS[nl]
                      + dot16(u0, Bs + ((size_t)((a0 << 7) + nl)) * LR);
            float v01 = acc[f][g][1] + biasS[nl + 1]
                      + dot16(u0, Bs + ((size_t)((a0 << 7) + nl + 1)) * LR);
            float v10 = acc[f][g][2] + biasS[nl]
                      + dot16(u1, Bs + ((size_t)((a1 << 7) + nl)) * LR);
            float v11 = acc[f][g][3] + biasS[nl + 1]
                      + dot16(u1, Bs + ((size_t)((a1 << 7) + nl + 1)) * LR);
            size_t o0 = (size_t)r0 * N + n0 + nl;
            size_t o1 = (size_t)r1 * N + n0 + nl;
            if (resid) {
                float2 q0 = *(const float2*)(resid + o0);
                float2 q1 = *(const float2*)(resid + o1);
                v00 += q0.x; v01 += q0.y; v10 += q1.x; v11 += q1.y;
            }
            if (relu) {
                v00 = fmaxf(v00, 0.f); v01 = fmaxf(v01, 0.f);
                v10 = fmaxf(v10, 0.f); v11 = fmaxf(v11, 0.f);
            }
            *(float2*)(C + o0) = make_float2(v00, v01);
            *(float2*)(C + o1) = make_float2(v10, v11);
        }
    }
}

// ---------------- LayerNorm: one block per row --------------------------------
__global__ void ln_kernel(const float* __restrict__ x, const float* __restrict__ g,
                          const float* __restrict__ b, float* __restrict__ out) {
    int row = blockIdx.x;
    const float* xr = x + (size_t)row * DIM;
    float* orow = out + (size_t)row * DIM;
    int tid = threadIdx.x;
    float s = 0.f, s2 = 0.f;
    for (int i = tid; i < DIM; i += 256) { float v = xr[i]; s += v; s2 += v * v; }
    __shared__ float rs[8], rs2[8];
    #pragma unroll
    for (int o = 16; o; o >>= 1) {
        s  += __shfl_xor_sync(0xffffffffu, s,  o);
        s2 += __shfl_xor_sync(0xffffffffu, s2, o);
    }
    int warp = tid >> 5, lane = tid & 31;
    if (!lane) { rs[warp] = s; rs2[warp] = s2; }
    __syncthreads();
    s = 0.f; s2 = 0.f;
    #pragma unroll
    for (int w = 0; w < 8; w++) { s += rs[w]; s2 += rs2[w]; }
    float mean = s * (1.f / DIM);
    float var  = s2 * (1.f / DIM) - mean * mean;
    float rstd = rsqrtf(var + 1e-5f);
    for (int i = tid; i < DIM; i += 256) {
        float v = xr[i];
        orow[i] = (v - mean) * rstd * g[i] + b[i];
    }
}

// ---------------- LoRA "u" = x @ A^T  (per-token adapter) ---------------------
__global__ void lora_u_kernel(const float* __restrict__ x, const float* __restrict__ A,
                              const int* __restrict__ map, float* __restrict__ u, int K) {
    int t = blockIdx.x;
    int a = map[t];
    const float* xr = x + (size_t)t * K;
    int warp = threadIdx.x >> 5, lane = threadIdx.x & 31;
    #pragma unroll
    for (int rr = 0; rr < 2; rr++) {
        int r = warp * 2 + rr;
        const float* ar = A + ((size_t)a * LR + r) * K;
        float s = 0.f;
        for (int i = lane; i < K; i += 32) s += xr[i] * ar[i];
        #pragma unroll
        for (int o = 16; o; o >>= 1) s += __shfl_xor_sync(0xffffffffu, s, o);
        if (!lane) u[t * LR + r] = s;
    }
}

// ---------------- causal attention: one block (128 thr) per (b,h,q) -----------
__global__ void attn_kernel(const float* __restrict__ qkv, float* __restrict__ out) {
    int qi = blockIdx.x, h = blockIdx.y, bb = blockIdx.z;
    __shared__ float qs[HD];
    __shared__ float sc[SEQ];
    __shared__ float red[4];
    const size_t base = (size_t)bb * SEQ * H3;
    int tid = threadIdx.x, lane = tid & 31, warp = tid >> 5;
    const float* qrow = qkv + base + (size_t)qi * H3 + h * HD;
    qs[tid] = qrow[tid];
    __syncthreads();
    int nk = qi + 1;
    const float scale = 0.08838834764831845f;   // 128^-0.5
    for (int k = warp; k < nk; k += 4) {
        const float* krow = qkv + base + (size_t)k * H3 + DIM + h * HD;
        float s = 0.f;
        #pragma unroll
        for (int dd = 0; dd < 4; dd++) { int d = lane + dd * 32; s += qs[d] * krow[d]; }
        #pragma unroll
        for (int o = 16; o; o >>= 1) s += __shfl_xor_sync(0xffffffffu, s, o);
        if (!lane) sc[k] = s * scale;
    }
    __syncthreads();
    float mx = -1e30f;
    for (int i = tid; i < nk; i += 128) mx = fmaxf(mx, sc[i]);
    #pragma unroll
    for (int o = 16; o; o >>= 1) mx = fmaxf(mx, __shfl_xor_sync(0xffffffffu, mx, o));
    if (!lane) red[warp] = mx;
    __syncthreads();
    mx = fmaxf(fmaxf(red[0], red[1]), fmaxf(red[2], red[3]));
    __syncthreads();
    float sum = 0.f;
    for (int i = tid; i < nk; i += 128) { float e = expf(sc[i] - mx); sc[i] = e; sum += e; }
    #pragma unroll
    for (int o = 16; o; o >>= 1) sum += __shfl_xor_sync(0xffffffffu, sum, o);
    if (!lane) red[warp] = sum;
    __syncthreads();
    sum = red[0] + red[1] + red[2] + red[3];
    float inv = 1.f / sum;
    float acc = 0.f;
    const float* vbase = qkv + base + 2 * DIM + h * HD + tid;
    for (int k = 0; k < nk; k++) acc += sc[k] * vbase[(size_t)k * H3];
    out[((size_t)bb * SEQ + qi) * DIM + h * HD + tid] = acc * inv;
}

// ---------------- launch ------------------------------------------------------
extern "C" void kernel_launch(void* const* d_in, const int* in_sizes, int n_in,
                              void* d_out, int out_size) {
    const float* x    = (const float*)d_in[0];
    const int*   map  = (const int*)  d_in[1];
    const float* Wqkv = (const float*)d_in[2];
    const float* bqkv = (const float*)d_in[3];
    const float* Wout = (const float*)d_in[4];
    const float* bout = (const float*)d_in[5];
    const float* Wfc1 = (const float*)d_in[6];
    const float* bfc1 = (const float*)d_in[7];
    const float* Wfc2 = (const float*)d_in[8];
    const float* bfc2 = (const float*)d_in[9];
    const float* ln1g = (const float*)d_in[10];
    const float* ln1b = (const float*)d_in[11];
    const float* ln2g = (const float*)d_in[12];
    const float* ln2b = (const float*)d_in[13];
    const float* Aqkv = (const float*)d_in[14];
    const float* Bqkv = (const float*)d_in[15];
    const float* Aout = (const float*)d_in[16];
    const float* Bout = (const float*)d_in[17];
    const float* Afc1 = (const float*)d_in[18];
    const float* Bfc1 = (const float*)d_in[19];
    const float* Afc2 = (const float*)d_in[20];
    const float* Bfc2 = (const float*)d_in[21];
    float* out = (float*)d_out;

    float *p_ln1, *p_qkv, *p_attn, *p_res2, *p_ln2, *p_h1, *p_u;
    cudaGetSymbolAddress((void**)&p_ln1,  g_ln1);
    cudaGetSymbolAddress((void**)&p_qkv,  g_qkv);
    cudaGetSymbolAddress((void**)&p_attn, g_attn);
    cudaGetSymbolAddress((void**)&p_res2, g_res2);
    cudaGetSymbolAddress((void**)&p_ln2,  g_ln2);
    cudaGetSymbolAddress((void**)&p_h1,   g_h1);
    cudaGetSymbolAddress((void**)&p_u,    g_u);

    cudaFuncSetAttribute(tc_gemm, cudaFuncAttributeMaxDynamicSharedMemorySize,
                         SMEM_G);

    // ---- attention block ----
    ln_kernel<<<NT, 256>>>(x, ln1g, ln1b, p_ln1);
    lora_u_kernel<<<NT, 256>>>(p_ln1, Aqkv, map, p_u, DIM);
    tc_gemm<<<dim3(H3 / BN, NT / BM), 256, SMEM_G>>>(
        p_ln1, Wqkv, bqkv, p_u, Bqkv, map, nullptr, p_qkv, H3, DIM, 0);
    attn_kernel<<<dim3(SEQ, NH, 2), 128>>>(p_qkv, p_attn);
    lora_u_kernel<<<NT, 256>>>(p_attn, Aout, map, p_u, DIM);
    tc_gemm<<<dim3(DIM / BN, NT / BM), 256, SMEM_G>>>(
        p_attn, Wout, bout, p_u, Bout, map, x, p_res2, DIM, DIM, 0);
    // ---- FFN block ----
    ln_kernel<<<NT, 256>>>(p_res2, ln2g, ln2b, p_ln2);
    lora_u_kernel<<<NT, 256>>>(p_ln2, Afc1, map, p_u, DIM);
    tc_gemm<<<dim3(FFN_D / BN, NT / BM), 256, SMEM_G>>>(
        p_ln2, Wfc1, bfc1, p_u, Bfc1, map, nullptr, p_h1, FFN_D, DIM, 1);
    lora_u_kernel<<<NT, 256>>>(p_h1, Afc2, map, p_u, FFN_D);
    tc_gemm<<<dim3(DIM / BN, NT / BM), 256, SMEM_G>>>(
        p_h1, Wfc2, bfc2, p_u, Bfc2, map, p_res2, out, DIM, FFN_D, 0);
}

// round 5
// speedup vs baseline: 2.5129x; 1.0422x over previous
#include <cuda_runtime.h>
#include <cuda_bf16.h>
#include <cstdint>
#include <cstddef>

#define DIM   4096
#define H3    12288
#define FFN_D 16384
#define NT    2048      // total tokens = 2*1024
#define LR    16        // lora rank
#define SEQ   1024
#define NH    32
#define HD    128

// ---------------- scratch (device globals; no allocations allowed) ----------
__device__ float g_ln1 [(size_t)NT * DIM];
__device__ float g_qkv [(size_t)NT * H3];
__device__ float g_attn[(size_t)NT * DIM];
__device__ float g_res2[(size_t)NT * DIM];
__device__ float g_ln2 [(size_t)NT * DIM];
__device__ float g_h1  [(size_t)NT * FFN_D];
__device__ float g_u   [(size_t)NT * LR];

// split-bf16 planes
#define WOFF_QKV 0
#define WOFF_OUT 50331648u
#define WOFF_FC1 67108864u
#define WOFF_FC2 134217728u
#define W_TOTAL  201326592u
__device__ __nv_bfloat16 g_Whi[W_TOTAL];
__device__ __nv_bfloat16 g_Wlo[W_TOTAL];
__device__ __nv_bfloat16 g_Ahi[(size_t)NT * FFN_D];
__device__ __nv_bfloat16 g_Alo[(size_t)NT * FFN_D];

// ================= helpers ===================================================
__device__ __forceinline__ uint32_t smem_u32(const void* p) {
    uint32_t a;
    asm("{ .reg .u64 t; cvta.to.shared.u64 t, %1; cvt.u32.u64 %0, t; }"
        : "=r"(a) : "l"(p));
    return a;
}
__device__ __forceinline__ void ldmx4(uint32_t* r, uint32_t addr) {
    asm volatile("ldmatrix.sync.aligned.m8n8.x4.shared.b16 {%0,%1,%2,%3}, [%4];"
                 : "=r"(r[0]), "=r"(r[1]), "=r"(r[2]), "=r"(r[3]) : "r"(addr));
}
__device__ __forceinline__ uint32_t lds32(uint32_t addr) {
    uint32_t v;
    asm volatile("ld.shared.b32 %0, [%1];" : "=r"(v) : "r"(addr));
    return v;
}
__device__ __forceinline__ void mma16816(float* d, const uint32_t* a,
                                         uint32_t b0, uint32_t b1) {
    asm volatile("mma.sync.aligned.m16n8k16.row.col.f32.bf16.bf16.f32 "
                 "{%0,%1,%2,%3}, {%4,%5,%6,%7}, {%8,%9}, {%0,%1,%2,%3};"
                 : "+f"(d[0]), "+f"(d[1]), "+f"(d[2]), "+f"(d[3])
                 : "r"(a[0]), "r"(a[1]), "r"(a[2]), "r"(a[3]),
                   "r"(b0), "r"(b1));
}
__device__ __forceinline__ void cpa16(uint32_t d, const void* s) {
    asm volatile("cp.async.ca.shared.global [%0], [%1], 16;"
                 :: "r"(d), "l"(s) : "memory");
}
__device__ __forceinline__ void cpa_commit() {
    asm volatile("cp.async.commit_group;" ::: "memory");
}

// ================= fp32 -> (hi, lo) bf16 split conversion =====================
__global__ void cvt_split(const float* __restrict__ src,
                          __nv_bfloat16* __restrict__ hi,
                          __nv_bfloat16* __restrict__ lo, size_t n4) {
    size_t i = (size_t)blockIdx.x * blockDim.x + threadIdx.x;
    size_t stride = (size_t)gridDim.x * blockDim.x;
    for (; i < n4; i += stride) {
        float4 v = ((const float4*)src)[i];
        __nv_bfloat16 h0 = __float2bfloat16(v.x), h1 = __float2bfloat16(v.y);
        __nv_bfloat16 h2 = __float2bfloat16(v.z), h3 = __float2bfloat16(v.w);
        float l0 = v.x - __bfloat162float(h0), l1 = v.y - __bfloat162float(h1);
        float l2 = v.z - __bfloat162float(h2), l3 = v.w - __bfloat162float(h3);
        __nv_bfloat162 hA(h0, h1), hB(h2, h3);
        __nv_bfloat162 lA(__float2bfloat16(l0), __float2bfloat16(l1));
        __nv_bfloat162 lB(__float2bfloat16(l2), __float2bfloat16(l3));
        uint2 hw, lw;
        hw.x = *(uint32_t*)&hA; hw.y = *(uint32_t*)&hB;
        lw.x = *(uint32_t*)&lA; lw.y = *(uint32_t*)&lB;
        ((uint2*)hi)[i] = hw;
        ((uint2*)lo)[i] = lw;
    }
}

// ================= tensor-core GEMM (pre-split bf16, 3-term) ==================
// C[m,n] = sum_k A[m,k]*W[n,k] + bias[n] + sum_r u[m,r]*Bl[map[m],n,r]
//          (+ resid[m,n]) (relu?)
// Block 128x128, BK=32, 8 warps (2m x 4n), warp tile 64x32, mma m16n8k16.
#define BM 128
#define BN 128
#define BKC 32
#define RSTR 40                       // smem row stride in bf16 (pad vs banks)
#define PLANE (128 * RSTR * 2)        // 10240 B per bf16 plane
#define STAGE_B (4 * PLANE)           // A_hi | A_lo | W_hi | W_lo
#define SOFF_BIAS  128
#define SOFF_STAGE 1024
#define SMEM_G (SOFF_STAGE + 2 * STAGE_B)   // 82944

__device__ __forceinline__ float dot16(const float* u, const float* b) {
    float s = 0.f;
    #pragma unroll
    for (int r = 0; r < 16; r++) s = fmaf(u[r], b[r], s);
    return s;
}

__device__ __forceinline__ void issue_chunk(
        const __nv_bfloat16* __restrict__ Ahi, const __nv_bfloat16* __restrict__ Alo,
        const __nv_bfloat16* __restrict__ Whi, const __nv_bfloat16* __restrict__ Wlo,
        int m0, int n0, int K, int c, uint32_t sdst, int tid) {
    int k0 = c * BKC;
    #pragma unroll
    for (int p = 0; p < 2; p++) {
        int idx = tid + p * 256;
        int row = idx >> 2, seg = idx & 3;
        uint32_t d = sdst + row * (RSTR * 2) + seg * 16;
        size_t ao = (size_t)(m0 + row) * K + k0 + seg * 8;
        size_t wo = (size_t)(n0 + row) * K + k0 + seg * 8;
        cpa16(d,             Ahi + ao);
        cpa16(d + PLANE,     Alo + ao);
        cpa16(d + 2 * PLANE, Whi + wo);
        cpa16(d + 3 * PLANE, Wlo + wo);
    }
    cpa_commit();
}

__global__ void __launch_bounds__(256, 2)
tc_gemm(const __nv_bfloat16* __restrict__ Ahi, const __nv_bfloat16* __restrict__ Alo,
        const __nv_bfloat16* __restrict__ Whi, const __nv_bfloat16* __restrict__ Wlo,
        const float* __restrict__ bias, const float* __restrict__ u,
        const float* __restrict__ Bl, const int* __restrict__ map,
        const float* __restrict__ resid, float* __restrict__ C,
        int N, int K, int relu) {
    extern __shared__ __align__(1024) char smem[];
    uint32_t sbase = smem_u32(smem);
    int tid = threadIdx.x;
    int lane = tid & 31, warp = tid >> 5;
    int wm = warp >> 2, wn = warp & 3;
    int n0 = blockIdx.x * BN;
    int m0 = blockIdx.y * BM;

    if (tid < BN) ((float*)(smem + SOFF_BIAS))[tid] = bias[n0 + tid];

    float acc[4][4][4];
    #pragma unroll
    for (int f = 0; f < 4; f++)
        #pragma unroll
        for (int g = 0; g < 4; g++)
            #pragma unroll
            for (int e = 0; e < 4; e++) acc[f][g][e] = 0.f;

    int nCh = K >> 5;
    issue_chunk(Ahi, Alo, Whi, Wlo, m0, n0, K, 0, sbase + SOFF_STAGE, tid);
    if (nCh > 1)
        issue_chunk(Ahi, Alo, Whi, Wlo, m0, n0, K, 1,
                    sbase + SOFF_STAGE + STAGE_B, tid);

    int lane15 = lane & 15, laneHalf = lane >> 4;
    int grp = lane >> 2, tig = lane & 3;

    for (int c = 0; c < nCh; c++) {
        int cur = c & 1;
        if (c + 1 < nCh)
            asm volatile("cp.async.wait_group 1;" ::: "memory");
        else
            asm volatile("cp.async.wait_group 0;" ::: "memory");
        __syncthreads();

        uint32_t base = sbase + SOFF_STAGE + cur * STAGE_B;
        #pragma unroll
        for (int ks = 0; ks < 2; ks++) {
            uint32_t ahi[4][4], alo[4][4];
            int koffA = ks * 16 + laneHalf * 8;
            #pragma unroll
            for (int f = 0; f < 4; f++) {
                int row = wm * 64 + f * 16 + lane15;
                uint32_t ad = base + row * (RSTR * 2) + koffA * 2;
                ldmx4(ahi[f], ad);
                ldmx4(alo[f], ad + PLANE);
            }
            #pragma unroll
            for (int g = 0; g < 4; g++) {
                int n = wn * 32 + g * 8 + grp;
                uint32_t bd = base + 2 * PLANE + n * (RSTR * 2)
                            + (ks * 16 + tig * 2) * 2;
                uint32_t bh0 = lds32(bd), bh1 = lds32(bd + 16);
                uint32_t bl0 = lds32(bd + PLANE), bl1 = lds32(bd + PLANE + 16);
                #pragma unroll
                for (int f = 0; f < 4; f++) {
                    mma16816(acc[f][g], ahi[f], bh0, bh1);
                    mma16816(acc[f][g], ahi[f], bl0, bl1);
                    mma16816(acc[f][g], alo[f], bh0, bh1);
                }
            }
        }
        __syncthreads();
        if (c + 2 < nCh)
            issue_chunk(Ahi, Alo, Whi, Wlo, m0, n0, K, c + 2,
                        sbase + SOFF_STAGE + cur * STAGE_B, tid);
    }

    // ---- stage lora-B slice into SMEM (reuses stage area) ----
    float* Bs = (float*)(smem + SOFF_STAGE);
    for (int i = tid; i < 4096; i += 256) {   // 8 adapters * 128 n * 4 float4
        int a   = i >> 9;
        int rem = i & 511;
        int nl  = rem >> 2;
        int sg  = rem & 3;
        float4 v = *(const float4*)(Bl + ((size_t)a * N + n0 + nl) * LR + sg * 4);
        *(float4*)(Bs + ((size_t)((a << 7) + nl)) * LR + sg * 4) = v;
    }
    __syncthreads();

    const float* biasS = (const float*)(smem + SOFF_BIAS);
    #pragma unroll
    for (int f = 0; f < 4; f++) {
        int r0 = m0 + wm * 64 + f * 16 + grp;
        int r1 = r0 + 8;
        int a0 = map[r0], a1 = map[r1];
        float u0[16], u1[16];
        {
            const float4* p0 = (const float4*)(u + (size_t)r0 * LR);
            const float4* p1 = (const float4*)(u + (size_t)r1 * LR);
            #pragma unroll
            for (int q = 0; q < 4; q++) {
                float4 v0 = p0[q], v1 = p1[q];
                u0[q*4+0]=v0.x; u0[q*4+1]=v0.y; u0[q*4+2]=v0.z; u0[q*4+3]=v0.w;
                u1[q*4+0]=v1.x; u1[q*4+1]=v1.y; u1[q*4+2]=v1.z; u1[q*4+3]=v1.w;
            }
        }
        #pragma unroll
        for (int g = 0; g < 4; g++) {
            int nl = wn * 32 + g * 8 + tig * 2;
            float v00 = acc[f][g][0] + biasS[nl]
                      + dot16(u0, Bs + ((size_t)((a0 << 7) + nl)) * LR);
            float v01 = acc[f][g][1] + biasS[nl + 1]
                      + dot16(u0, Bs + ((size_t)((a0 << 7) + nl + 1)) * LR);
            float v10 = acc[f][g][2] + biasS[nl]
                      + dot16(u1, Bs + ((size_t)((a1 << 7) + nl)) * LR);
            float v11 = acc[f][g][3] + biasS[nl + 1]
                      + dot16(u1, Bs + ((size_t)((a1 << 7) + nl + 1)) * LR);
            size_t o0 = (size_t)r0 * N + n0 + nl;
            size_t o1 = (size_t)r1 * N + n0 + nl;
            if (resid) {
                float2 q0 = *(const float2*)(resid + o0);
                float2 q1 = *(const float2*)(resid + o1);
                v00 += q0.x; v01 += q0.y; v10 += q1.x; v11 += q1.y;
            }
            if (relu) {
                v00 = fmaxf(v00, 0.f); v01 = fmaxf(v01, 0.f);
                v10 = fmaxf(v10, 0.f); v11 = fmaxf(v11, 0.f);
            }
            *(float2*)(C + o0) = make_float2(v00, v01);
            *(float2*)(C + o1) = make_float2(v10, v11);
        }
    }
}

// ---------------- LayerNorm: one block per row --------------------------------
__global__ void ln_kernel(const float* __restrict__ x, const float* __restrict__ g,
                          const float* __restrict__ b, float* __restrict__ out) {
    int row = blockIdx.x;
    const float* xr = x + (size_t)row * DIM;
    float* orow = out + (size_t)row * DIM;
    int tid = threadIdx.x;
    float s = 0.f, s2 = 0.f;
    for (int i = tid; i < DIM; i += 256) { float v = xr[i]; s += v; s2 += v * v; }
    __shared__ float rs[8], rs2[8];
    #pragma unroll
    for (int o = 16; o; o >>= 1) {
        s  += __shfl_xor_sync(0xffffffffu, s,  o);
        s2 += __shfl_xor_sync(0xffffffffu, s2, o);
    }
    int warp = tid >> 5, lane = tid & 31;
    if (!lane) { rs[warp] = s; rs2[warp] = s2; }
    __syncthreads();
    s = 0.f; s2 = 0.f;
    #pragma unroll
    for (int w = 0; w < 8; w++) { s += rs[w]; s2 += rs2[w]; }
    float mean = s * (1.f / DIM);
    float var  = s2 * (1.f / DIM) - mean * mean;
    float rstd = rsqrtf(var + 1e-5f);
    for (int i = tid; i < DIM; i += 256) {
        float v = xr[i];
        orow[i] = (v - mean) * rstd * g[i] + b[i];
    }
}

// ---------------- LoRA "u" = x @ A^T  (per-token adapter) ---------------------
__global__ void lora_u_kernel(const float* __restrict__ x, const float* __restrict__ A,
                              const int* __restrict__ map, float* __restrict__ u, int K) {
    int t = blockIdx.x;
    int a = map[t];
    const float* xr = x + (size_t)t * K;
    int warp = threadIdx.x >> 5, lane = threadIdx.x & 31;
    #pragma unroll
    for (int rr = 0; rr < 2; rr++) {
        int r = warp * 2 + rr;
        const float* ar = A + ((size_t)a * LR + r) * K;
        float s = 0.f;
        for (int i = lane; i < K; i += 32) s += xr[i] * ar[i];
        #pragma unroll
        for (int o = 16; o; o >>= 1) s += __shfl_xor_sync(0xffffffffu, s, o);
        if (!lane) u[t * LR + r] = s;
    }
}

// ---------------- causal attention: q-tiled (TQ=8), scores in SMEM ------------
#define TQ 8
__global__ void attn2_kernel(const float* __restrict__ qkv, float* __restrict__ out) {
    int qt = blockIdx.x, h = blockIdx.y, bb = blockIdx.z;
    __shared__ float qs[TQ][HD];
    __shared__ float sc[TQ][SEQ];
    __shared__ float sinv[TQ];
    const size_t base = (size_t)bb * SEQ * H3;
    int tid = threadIdx.x, lane = tid & 31, warp = tid >> 5;
    int q0 = qt * TQ;

    for (int i = tid; i < TQ * HD; i += 256) {
        int r = i >> 7, d = i & 127;
        qs[r][d] = qkv[base + (size_t)(q0 + r) * H3 + h * HD + d];
    }
    __syncthreads();

    int nkmax = q0 + TQ;
    const float scale = 0.08838834764831845f;   // 128^-0.5
    // scores: warp-strided keys, lane-split dims, butterfly reduce
    for (int j = warp; j < nkmax; j += 8) {
        const float4 kv = *(const float4*)(qkv + base + (size_t)j * H3 + DIM
                                           + h * HD + lane * 4);
        float part[TQ];
        #pragma unroll
        for (int i = 0; i < TQ; i++) {
            float4 qv = *(const float4*)&qs[i][lane * 4];
            part[i] = qv.x * kv.x + qv.y * kv.y + qv.z * kv.z + qv.w * kv.w;
        }
        #pragma unroll
        for (int o = 16; o; o >>= 1)
            #pragma unroll
            for (int i = 0; i < TQ; i++)
                part[i] += __shfl_xor_sync(0xffffffffu, part[i], o);
        #pragma unroll
        for (int i = 0; i < TQ; i++)
            if (lane == i)
                sc[i][j] = (j <= q0 + i) ? part[i] * scale : -1e30f;
    }
    __syncthreads();

    // softmax: warp w owns row w
    {
        int i = warp;
        int nk = q0 + i + 1;
        float mx = -1e30f;
        for (int j = lane; j < nk; j += 32) mx = fmaxf(mx, sc[i][j]);
        #pragma unroll
        for (int o = 16; o; o >>= 1)
            mx = fmaxf(mx, __shfl_xor_sync(0xffffffffu, mx, o));
        float sum = 0.f;
        for (int j = lane; j < nk; j += 32) {
            float e = __expf(sc[i][j] - mx);
            sc[i][j] = e;
            sum += e;
        }
        #pragma unroll
        for (int o = 16; o; o >>= 1) sum += __shfl_xor_sync(0xffffffffu, sum, o);
        if (!lane) sinv[i] = 1.f / sum;
    }
    __syncthreads();

    // PV: warp w owns row w; lane owns 4 dims
    {
        int i = warp;
        int nk = q0 + i + 1;
        float4 acc = make_float4(0.f, 0.f, 0.f, 0.f);
        const float* vb = qkv + base + 2 * DIM + h * HD + lane * 4;
        int j = 0;
        for (; j + 2 <= nk; j += 2) {
            float p0 = sc[i][j], p1 = sc[i][j + 1];
            float4 v0 = *(const float4*)(vb + (size_t)j * H3);
            float4 v1 = *(const float4*)(vb + (size_t)(j + 1) * H3);
            acc.x += p0 * v0.x + p1 * v1.x;
            acc.y += p0 * v0.y + p1 * v1.y;
            acc.z += p0 * v0.z + p1 * v1.z;
            acc.w += p0 * v0.w + p1 * v1.w;
        }
        if (j < nk) {
            float p0 = sc[i][j];
            float4 v0 = *(const float4*)(vb + (size_t)j * H3);
            acc.x += p0 * v0.x; acc.y += p0 * v0.y;
            acc.z += p0 * v0.z; acc.w += p0 * v0.w;
        }
        float inv = sinv[i];
        acc.x *= inv; acc.y *= inv; acc.z *= inv; acc.w *= inv;
        *(float4*)(out + ((size_t)bb * SEQ + q0 + i) * DIM + h * HD + lane * 4) = acc;
    }
}

// ---------------- launch ------------------------------------------------------
extern "C" void kernel_launch(void* const* d_in, const int* in_sizes, int n_in,
                              void* d_out, int out_size) {
    const float* x    = (const float*)d_in[0];
    const int*   map  = (const int*)  d_in[1];
    const float* Wqkv = (const float*)d_in[2];
    const float* bqkv = (const float*)d_in[3];
    const float* Wout = (const float*)d_in[4];
    const float* bout = (const float*)d_in[5];
    const float* Wfc1 = (const float*)d_in[6];
    const float* bfc1 = (const float*)d_in[7];
    const float* Wfc2 = (const float*)d_in[8];
    const float* bfc2 = (const float*)d_in[9];
    const float* ln1g = (const float*)d_in[10];
    const float* ln1b = (const float*)d_in[11];
    const float* ln2g = (const float*)d_in[12];
    const float* ln2b = (const float*)d_in[13];
    const float* Aqkv = (const float*)d_in[14];
    const float* Bqkv = (const float*)d_in[15];
    const float* Aout = (const float*)d_in[16];
    const float* Bout = (const float*)d_in[17];
    const float* Afc1 = (const float*)d_in[18];
    const float* Bfc1 = (const float*)d_in[19];
    const float* Afc2 = (const float*)d_in[20];
    const float* Bfc2 = (const float*)d_in[21];
    float* out = (float*)d_out;

    float *p_ln1, *p_qkv, *p_attn, *p_res2, *p_ln2, *p_h1, *p_u;
    __nv_bfloat16 *p_Whi, *p_Wlo, *p_Ahi, *p_Alo;
    cudaGetSymbolAddress((void**)&p_ln1,  g_ln1);
    cudaGetSymbolAddress((void**)&p_qkv,  g_qkv);
    cudaGetSymbolAddress((void**)&p_attn, g_attn);
    cudaGetSymbolAddress((void**)&p_res2, g_res2);
    cudaGetSymbolAddress((void**)&p_ln2,  g_ln2);
    cudaGetSymbolAddress((void**)&p_h1,   g_h1);
    cudaGetSymbolAddress((void**)&p_u,    g_u);
    cudaGetSymbolAddress((void**)&p_Whi,  g_Whi);
    cudaGetSymbolAddress((void**)&p_Wlo,  g_Wlo);
    cudaGetSymbolAddress((void**)&p_Ahi,  g_Ahi);
    cudaGetSymbolAddress((void**)&p_Alo,  g_Alo);

    cudaFuncSetAttribute(tc_gemm, cudaFuncAttributeMaxDynamicSharedMemorySize,
                         SMEM_G);

    // ---- convert all weights to split-bf16 planes ----
    cvt_split<<<4096, 256>>>(Wqkv, p_Whi + WOFF_QKV, p_Wlo + WOFF_QKV,
                             (size_t)H3 * DIM / 4);
    cvt_split<<<4096, 256>>>(Wout, p_Whi + WOFF_OUT, p_Wlo + WOFF_OUT,
                             (size_t)DIM * DIM / 4);
    cvt_split<<<4096, 256>>>(Wfc1, p_Whi + WOFF_FC1, p_Wlo + WOFF_FC1,
                             (size_t)FFN_D * DIM / 4);
    cvt_split<<<4096, 256>>>(Wfc2, p_Whi + WOFF_FC2, p_Wlo + WOFF_FC2,
                             (size_t)DIM * FFN_D / 4);

    // ---- attention block ----
    ln_kernel<<<NT, 256>>>(x, ln1g, ln1b, p_ln1);
    lora_u_kernel<<<NT, 256>>>(p_ln1, Aqkv, map, p_u, DIM);
    cvt_split<<<2048, 256>>>(p_ln1, p_Ahi, p_Alo, (size_t)NT * DIM / 4);
    tc_gemm<<<dim3(H3 / BN, NT / BM), 256, SMEM_G>>>(
        p_Ahi, p_Alo, p_Whi + WOFF_QKV, p_Wlo + WOFF_QKV,
        bqkv, p_u, Bqkv, map, nullptr, p_qkv, H3, DIM, 0);
    attn2_kernel<<<dim3(SEQ / TQ, NH, 2), 256>>>(p_qkv, p_attn);
    lora_u_kernel<<<NT, 256>>>(p_attn, Aout, map, p_u, DIM);
    cvt_split<<<2048, 256>>>(p_attn, p_Ahi, p_Alo, (size_t)NT * DIM / 4);
    tc_gemm<<<dim3(DIM / BN, NT / BM), 256, SMEM_G>>>(
        p_Ahi, p_Alo, p_Whi + WOFF_OUT, p_Wlo + WOFF_OUT,
        bout, p_u, Bout, map, x, p_res2, DIM, DIM, 0);
    // ---- FFN block ----
    ln_kernel<<<NT, 256>>>(p_res2, ln2g, ln2b, p_ln2);
    lora_u_kernel<<<NT, 256>>>(p_ln2, Afc1, map, p_u, DIM);
    cvt_split<<<2048, 256>>>(p_ln2, p_Ahi, p_Alo, (size_t)NT * DIM / 4);
    tc_gemm<<<dim3(FFN_D / BN, NT / BM), 256, SMEM_G>>>(
        p_Ahi, p_Alo, p_Whi + WOFF_FC1, p_Wlo + WOFF_FC1,
        bfc1, p_u, Bfc1, map, nullptr, p_h1, FFN_D, DIM, 1);
    lora_u_kernel<<<NT, 256>>>(p_h1, Afc2, map, p_u, FFN_D);
    cvt_split<<<4096, 256>>>(p_h1, p_Ahi, p_Alo, (size_t)NT * FFN_D / 4);
    tc_gemm<<<dim3(DIM / BN, NT / BM), 256, SMEM_G>>>(
        p_Ahi, p_Alo, p_Whi + WOFF_FC2, p_Wlo + WOFF_FC2,
        bfc2, p_u, Bfc2, map, p_res2, out, DIM, FFN_D, 0);
}